// round 3
// baseline (speedup 1.0000x reference)
#include <cuda_runtime.h>
#include <cstddef>

// Problem constants (from reference): B=16, C=128, L=16384, K=8, S=4, ITERS=20
#define BB     16
#define CC     128
#define LL     16384
#define KK     8
#define STRIDE 4
#define WW     4095      // (L - K) / S + 1
#define ITERS  20

__device__ __forceinline__ float ex2_approx(float x) {
    float y;
    asm("ex2.approx.f32 %0, %1;" : "=f"(y) : "f"(x));
    return y;
}
__device__ __forceinline__ float rcp_approx(float x) {
    float y;
    asm("rcp.approx.f32 %0, %1;" : "=f"(y) : "f"(x));
    return y;
}

// One thread = one (b,c,w) window. 20-iteration bisection for
//   mean_k sigmoid(alpha*(m - x_k)) = q
// Key identity: with v = 2^(a2*mid - zc), Ek = 2^(a2*x_k - zc)  (a2 = alpha*log2e,
// zc = a2*window_center), sigmoid(alpha*(mid-x_k)) = v/(v+Ek).
// Pairwise combine: v/(v+Ei) + v/(v+Ej) = v*(2v+S)/(v^2 + v*S + P),
// S = Ei+Ej, P = Ei*Ej hoisted per window -> 4 RCP + 1 EX2 per iteration.
__global__ __launch_bounds__(256)
void iqp_kernel(const float* __restrict__ x,
                const float* __restrict__ q_raw,
                const float* __restrict__ alpha_raw,
                float* __restrict__ out)
{
    const int w  = blockIdx.x * blockDim.x + threadIdx.x;
    const int bc = blockIdx.y;             // b*C + c
    if (w >= WW) return;
    const int c = bc & (CC - 1);

    // Per-channel parameters (uniform within a row; cheap, once per thread)
    const float alpha = expf(alpha_raw[c]);
    const float q     = 1.0f / (1.0f + expf(-q_raw[c]));
    const float thr   = 8.0f * q;          // sum(s_k) > 8q  <=>  mean > q (exact)

    // Load the 8-element window: start = S*w -> 16B aligned -> two float4
    const float* row = x + (size_t)bc * LL + (size_t)(STRIDE * w);
    const float4 lo = *reinterpret_cast<const float4*>(row);
    const float4 hi = *reinterpret_cast<const float4*>(row + 4);
    const float x0 = lo.x, x1 = lo.y, x2 = lo.z, x3 = lo.w;
    const float x4 = hi.x, x5 = hi.y, x6 = hi.z, x7 = hi.w;

    const float mn = fminf(fminf(fminf(x0, x1), fminf(x2, x3)),
                           fminf(fminf(x4, x5), fminf(x6, x7)));
    const float mx = fmaxf(fmaxf(fmaxf(x0, x1), fmaxf(x2, x3)),
                           fmaxf(fmaxf(x4, x5), fmaxf(x6, x7)));

    const float inv2a = 2.0f / alpha;      // IEEE division (once)
    const float m_min = mn - inv2a;
    const float m_max = mx + inv2a;

    const float LOG2E = 1.4426950408889634f;
    const float a2 = alpha * LOG2E;
    const float zc = a2 * (0.5f * (mn + mx));   // center shift for dynamic range

    // Clamp exponents to +-60 (log2): v^2, P stay within fp32 normal range;
    // only distorts terms that are fully saturated anyway (window range > ~8.3).
    const float CL = 60.0f;

    float z, e0, e1, e2, e3, e4, e5, e6, e7;
    z = fmaf(x0, a2, -zc); z = fminf(fmaxf(z, -CL), CL); e0 = ex2_approx(z);
    z = fmaf(x1, a2, -zc); z = fminf(fmaxf(z, -CL), CL); e1 = ex2_approx(z);
    z = fmaf(x2, a2, -zc); z = fminf(fmaxf(z, -CL), CL); e2 = ex2_approx(z);
    z = fmaf(x3, a2, -zc); z = fminf(fmaxf(z, -CL), CL); e3 = ex2_approx(z);
    z = fmaf(x4, a2, -zc); z = fminf(fmaxf(z, -CL), CL); e4 = ex2_approx(z);
    z = fmaf(x5, a2, -zc); z = fminf(fmaxf(z, -CL), CL); e5 = ex2_approx(z);
    z = fmaf(x6, a2, -zc); z = fminf(fmaxf(z, -CL), CL); e6 = ex2_approx(z);
    z = fmaf(x7, a2, -zc); z = fminf(fmaxf(z, -CL), CL); e7 = ex2_approx(z);

    const float S0 = e0 + e1, P0 = e0 * e1;
    const float S1 = e2 + e3, P1 = e2 * e3;
    const float S2 = e4 + e5, P2 = e4 * e5;
    const float S3 = e6 + e7, P3 = e6 * e7;

    // Incremental bisection: mid_t+1 = mid_t +- h, h halves each step.
    // After 20 compares, mid is the center of the final interval = 0.5*(mn+mx).
    float mid = 0.5f * (m_min + m_max);
    float h   = 0.25f * (m_max - m_min);

    #pragma unroll
    for (int it = 0; it < ITERS; ++it) {
        float zv = fmaf(mid, a2, -zc);
        zv = fminf(fmaxf(zv, -CL), CL);
        const float v   = ex2_approx(zv);
        const float v2  = v * v;
        const float tv2 = v2 + v2;

        // den_p = v^2 + v*S_p + P_p ; num_p = 2v^2 + v*S_p ; pairsum = num/den
        const float d0 = fmaf(v, S0, v2) + P0;
        const float d1 = fmaf(v, S1, v2) + P1;
        const float d2 = fmaf(v, S2, v2) + P2;
        const float d3 = fmaf(v, S3, v2) + P3;

        const float r0 = rcp_approx(d0);
        const float r1 = rcp_approx(d1);
        const float r2 = rcp_approx(d2);
        const float r3 = rcp_approx(d3);

        const float n0 = fmaf(v, S0, tv2);
        const float n1 = fmaf(v, S1, tv2);
        const float n2 = fmaf(v, S2, tv2);
        const float n3 = fmaf(v, S3, tv2);

        float acc = n0 * r0;
        acc = fmaf(n1, r1, acc);
        acc = fmaf(n2, r2, acc);
        acc = fmaf(n3, r3, acc);

        const bool too_high = acc > thr;       // vals > q
        mid = too_high ? (mid - h) : (mid + h);
        h *= 0.5f;
    }

    out[(size_t)bc * WW + w] = mid;
}

extern "C" void kernel_launch(void* const* d_in, const int* in_sizes, int n_in,
                              void* d_out, int out_size)
{
    const float* x         = (const float*)d_in[0];
    const float* q_raw     = (const float*)d_in[1];
    const float* alpha_raw = (const float*)d_in[2];
    float* out             = (float*)d_out;

    dim3 block(256);
    dim3 grid((WW + block.x - 1) / block.x, BB * CC);
    iqp_kernel<<<grid, block>>>(x, q_raw, alpha_raw, out);
}

// round 5
// speedup vs baseline: 1.1971x; 1.1971x over previous
#include <cuda_runtime.h>
#include <cstddef>
#include <cstdint>

// Problem constants: B=16, C=128, L=16384, K=8, S=4, ITERS=20
#define BB     16
#define CC     128
#define LL     16384
#define STRIDE 4
#define WW     4095      // (L - K) / S + 1
#define ITERS  20

#define LOG2E_F 1.4426950408889634f
#define ZCLAMP  60.0f    // pairwise form: v^2, E_i*E_j stay in fp32 range up to +-60
                         // (quartic needed <=31 -> R3's failure; pairs are safe)

// ---------------- scalar MUFU helpers ----------------
__device__ __forceinline__ float ex2_approx(float x) {
    float y; asm("ex2.approx.f32 %0, %1;" : "=f"(y) : "f"(x)); return y;
}
__device__ __forceinline__ float rcp_approx(float x) {
    float y; asm("rcp.approx.f32 %0, %1;" : "=f"(y) : "f"(x)); return y;
}

// ---------------- packed f32x2 helpers ----------------
typedef unsigned long long u64t;

__device__ __forceinline__ u64t pack2(float lo, float hi) {
    u64t r;
    asm("mov.b64 %0, {%1, %2};" : "=l"(r)
        : "r"(__float_as_uint(lo)), "r"(__float_as_uint(hi)));
    return r;
}
__device__ __forceinline__ void unpack2(u64t v, float& lo, float& hi) {
    unsigned a, b;
    asm("mov.b64 {%0, %1}, %2;" : "=r"(a), "=r"(b) : "l"(v));
    lo = __uint_as_float(a); hi = __uint_as_float(b);
}
__device__ __forceinline__ u64t fma2(u64t a, u64t b, u64t c) {
    u64t d; asm("fma.rn.f32x2 %0, %1, %2, %3;" : "=l"(d) : "l"(a), "l"(b), "l"(c));
    return d;
}
__device__ __forceinline__ u64t add2(u64t a, u64t b) {
    u64t d; asm("add.rn.f32x2 %0, %1, %2;" : "=l"(d) : "l"(a), "l"(b));
    return d;
}
__device__ __forceinline__ u64t mul2(u64t a, u64t b) {
    u64t d; asm("mul.rn.f32x2 %0, %1, %2;" : "=l"(d) : "l"(a), "l"(b));
    return d;
}

// ---------------- per-channel precompute ----------------
__device__ float g_a2[CC];      // alpha * log2(e)
__device__ float g_inv_a2[CC];  // 1 / (alpha * log2(e))
__device__ float g_thr[CC];     // 8 * sigmoid(q_raw)

__global__ void iqp_setup_kernel(const float* __restrict__ q_raw,
                                 const float* __restrict__ alpha_raw) {
    int c = threadIdx.x;
    if (c < CC) {
        float alpha = expf(alpha_raw[c]);
        float a2 = alpha * LOG2E_F;
        g_a2[c]     = a2;
        g_inv_a2[c] = 1.0f / a2;
        g_thr[c]    = 8.0f / (1.0f + expf(-q_raw[c]));
    }
}

// One thread = one (b,c,w) window. Bisection for mean_k sigmoid(alpha*(m-x_k)) = q
// in z-space: z = a2*(m-center), v = 2^z, E_k = 2^(a2*(x_k-center)).
// Pairwise rational (proven numerics, R2):
//   v/(v+Ei) + v/(v+Ej) = v*(2v+S)/(v^2 + v*S + P),  S=Ei+Ej, P=Ei*Ej hoisted.
// Four pairs; the two (num,den) Horner chains are f32x2 lane-packed:
//   packed A = pairs (01,23), packed B = pairs (45,67).
// Per iteration: 1 EX2 + 4 RCP (MUFU, the binding pipe) + 8 packed FMA-class.
__global__ __launch_bounds__(256)
void iqp_kernel(const float* __restrict__ x,
                float* __restrict__ out)
{
    const int w  = blockIdx.x * blockDim.x + threadIdx.x;
    const int bc = blockIdx.y;               // b*C + c
    if (w >= WW) return;
    const int c = bc & (CC - 1);

    const float a2     = g_a2[c];
    const float inv_a2 = g_inv_a2[c];
    const float thr    = g_thr[c];           // compare sum(s_k) vs 8q (exact)

    // 8-tap window: start = 4*w -> 16B aligned -> two float4 loads
    const float* row = x + (size_t)bc * LL + (size_t)(STRIDE * w);
    const float4 lo = *reinterpret_cast<const float4*>(row);
    const float4 hi = *reinterpret_cast<const float4*>(row + 4);
    const float x0 = lo.x, x1 = lo.y, x2 = lo.z, x3 = lo.w;
    const float x4 = hi.x, x5 = hi.y, x6 = hi.z, x7 = hi.w;

    const float mn = fminf(fminf(fminf(x0, x1), fminf(x2, x3)),
                           fminf(fminf(x4, x5), fminf(x6, x7)));
    const float mx = fmaxf(fmaxf(fmaxf(x0, x1), fmaxf(x2, x3)),
                           fmaxf(fmaxf(x4, x5), fmaxf(x6, x7)));

    const float center = 0.5f * (mn + mx);
    const float zc     = a2 * center;

    // E_k = 2^clamp(a2*(x_k - center), +-60). No clamp effect for window
    // range <= ~8.3 (P ~ 4e-9/window for N(0,1) -> numerically identical to R2).
    float z, e0, e1, e2, e3, e4, e5, e6, e7;
    z = fmaf(x0, a2, -zc); z = fminf(fmaxf(z, -ZCLAMP), ZCLAMP); e0 = ex2_approx(z);
    z = fmaf(x1, a2, -zc); z = fminf(fmaxf(z, -ZCLAMP), ZCLAMP); e1 = ex2_approx(z);
    z = fmaf(x2, a2, -zc); z = fminf(fmaxf(z, -ZCLAMP), ZCLAMP); e2 = ex2_approx(z);
    z = fmaf(x3, a2, -zc); z = fminf(fmaxf(z, -ZCLAMP), ZCLAMP); e3 = ex2_approx(z);
    z = fmaf(x4, a2, -zc); z = fminf(fmaxf(z, -ZCLAMP), ZCLAMP); e4 = ex2_approx(z);
    z = fmaf(x5, a2, -zc); z = fminf(fmaxf(z, -ZCLAMP), ZCLAMP); e5 = ex2_approx(z);
    z = fmaf(x6, a2, -zc); z = fminf(fmaxf(z, -ZCLAMP), ZCLAMP); e6 = ex2_approx(z);
    z = fmaf(x7, a2, -zc); z = fminf(fmaxf(z, -ZCLAMP), ZCLAMP); e7 = ex2_approx(z);

    // Pair sums/products, packed: lane0 = pair(0,1)/(4,5), lane1 = pair(2,3)/(6,7)
    const u64t pS_A = pack2(e0 + e1, e2 + e3);
    const u64t pP_A = pack2(e0 * e1, e2 * e3);
    const u64t pS_B = pack2(e4 + e5, e6 + e7);
    const u64t pP_B = pack2(e4 * e5, e6 * e7);

    // z-space bisection: zmid0 = 0 (mid0 = center exactly, since bracket pads
    // +-2/alpha cancel), zh0 = a2*(m_max-m_min)/4 = a2*range/4 + log2(e).
    float zmid = 0.0f;
    float zh   = fmaf(a2 * (mx - mn), 0.25f, LOG2E_F);

    #pragma unroll
    for (int it = 0; it < ITERS; ++it) {
        // Upper clamp only: keeps v^2 finite; tiny v is benign (den >= P > 0).
        const float vz = fminf(zmid, ZCLAMP);
        const float v  = ex2_approx(vz);
        const u64t vv  = pack2(v, v);
        const u64t vv2 = mul2(vv, vv);
        const u64t tv2 = add2(vv2, vv2);

        // den = v^2 + v*S + P ; num = 2v^2 + v*S  (per pair, lane-packed)
        const u64t dA = add2(fma2(vv, pS_A, vv2), pP_A);
        const u64t dB = add2(fma2(vv, pS_B, vv2), pP_B);
        const u64t nA = fma2(vv, pS_A, tv2);
        const u64t nB = fma2(vv, pS_B, tv2);

        float d0, d1, d2, d3, n0, n1, n2, n3;
        unpack2(dA, d0, d1);
        unpack2(dB, d2, d3);
        unpack2(nA, n0, n1);
        unpack2(nB, n2, n3);

        const float r0 = rcp_approx(d0);
        const float r1 = rcp_approx(d1);
        const float r2 = rcp_approx(d2);
        const float r3 = rcp_approx(d3);

        float acc = n0 * r0;
        acc = fmaf(n1, r1, acc);
        acc = fmaf(n2, r2, acc);
        acc = fmaf(n3, r3, acc);                 // sum of 8 sigmoids, in [0,8]

        // too_high <=> acc > thr <=> (thr - acc) < 0: inject sign into step.
        // Ties (diff == +0) step upward, matching reference (vals > q false).
        const float diff = thr - acc;
        const float step = __uint_as_float(__float_as_uint(zh) |
                                           (__float_as_uint(diff) & 0x80000000u));
        zmid += step;
        zh *= 0.5f;
    }

    out[(size_t)bc * WW + w] = fmaf(zmid, inv_a2, center);
}

extern "C" void kernel_launch(void* const* d_in, const int* in_sizes, int n_in,
                              void* d_out, int out_size)
{
    const float* x         = (const float*)d_in[0];
    const float* q_raw     = (const float*)d_in[1];
    const float* alpha_raw = (const float*)d_in[2];
    float* out             = (float*)d_out;

    iqp_setup_kernel<<<1, CC>>>(q_raw, alpha_raw);

    dim3 block(256);
    dim3 grid((WW + block.x - 1) / block.x, BB * CC);
    iqp_kernel<<<grid, block>>>(x, out);
}